// round 1
// baseline (speedup 1.0000x reference)
#include <cuda_runtime.h>

// ---------------------------------------------------------------------------
// Permutohedral-lattice bilateral filter, d=4 (z,y,x,intensity), dp1=5.
// Input 0: input_ (4,96,96,96) f32;  Input 1: image (1,96,96,96) f32.
// Output: (4,96,96,96) f32.
// ---------------------------------------------------------------------------

#define DIMX 96
#define NPIX (96*96*96)          // 884736
#define NBLK ((NPIX + 255) / 256)

#define HASH_BITS 23
#define HASH_SIZE (1u << HASH_BITS)   // 8388608 slots > 5*NPIX max keys
#define HASH_MASK (HASH_SIZE - 1u)
#define MAXM 4500000                  // >= 5*NPIX = 4423680
#define VSTRIDE 8                     // 32B-aligned per-vertex value row (5 used)

#define SC0 2.886751345948129f   // sqrt(2/3)*5/sqrt(2)
#define SC1 1.6666666666666667f  // sqrt(2/3)*5/sqrt(6) = 5/3
#define SC2 1.1785113019775793f  // sqrt(2/3)*5/sqrt(12)
#define SC3 0.9128709291752769f  // sqrt(2/3)*5/sqrt(20)
#define EPS64 2.220446049250313e-16f

__device__ unsigned long long g_keys[HASH_SIZE];
__device__ int                g_slotidx[HASH_SIZE];
__device__ unsigned long long g_ckey[MAXM];
__device__ float              g_valsA[(size_t)MAXM * VSTRIDE];
__device__ float              g_valsB[(size_t)MAXM * VSTRIDE];
__device__ int                g_pixidx[NPIX * 5];
__device__ float              g_pixbary[NPIX * 5];
__device__ int                g_count;

__device__ __forceinline__ unsigned hash64(unsigned long long k) {
    k *= 0x9E3779B97F4A7C15ull;
    return (unsigned)(k >> (64 - HASH_BITS));
}

__device__ __forceinline__ unsigned long long packkey(int c0, int c1, int c2, int c3) {
    return (((unsigned long long)(unsigned)(c0 + 2048)) << 48)
         | (((unsigned long long)(unsigned)(c1 + 2048)) << 32)
         | (((unsigned long long)(unsigned)(c2 + 2048)) << 16)
         |  ((unsigned long long)(unsigned)(c3 + 2048));
}

// Read-only probe. Returns compact index or -1 (miss).
__device__ __forceinline__ int hash_lookup(unsigned long long key) {
    unsigned s = hash64(key);
    #pragma unroll 1
    while (true) {
        unsigned long long k = g_keys[s];
        if (k == key) return g_slotidx[s];
        if (k == 0ull) return -1;
        s = (s + 1) & HASH_MASK;
    }
}

// Exact fp32 replication of the reference elevation/rank/bary/key math.
__device__ __forceinline__ void compute_lattice(int n, const float* __restrict__ image,
                                                unsigned long long keys[5], float bary[5]) {
    int x = n % DIMX;
    int t = n / DIMX;
    int y = t % DIMX;
    int z = t / DIMX;

    float cf0 = ((float)z / 5.0f) * SC0;
    float cf1 = ((float)y / 5.0f) * SC1;
    float cf2 = ((float)x / 5.0f) * SC2;
    float cf3 = (image[n] * 4.0f) * SC3;   // image / 0.25

    float e[5];
    float sm = 0.0f;
    e[4] = sm - 4.0f * cf3; sm += cf3;
    e[3] = sm - 3.0f * cf2; sm += cf2;
    e[2] = sm - 2.0f * cf1; sm += cf1;
    e[1] = sm - 1.0f * cf0; sm += cf0;
    e[0] = sm;

    float rem0[5], diff[5];
    int sum_rd = 0;
    #pragma unroll
    for (int i = 0; i < 5; i++) {
        float rd = rintf(e[i] / 5.0f);      // round-half-even, matches jnp.round
        rem0[i] = rd * 5.0f;
        diff[i] = e[i] - rem0[i];
        sum_rd += (int)rd;
    }

    int rank[5];
    #pragma unroll
    for (int i = 0; i < 5; i++) {
        int c = 0;
        #pragma unroll
        for (int j = 0; j < 5; j++)
            c += (diff[j] > diff[i]) || ((diff[j] == diff[i]) && (j < i));
        c += sum_rd;
        if (c < 0)      { c += 5; rem0[i] += 5.0f; }
        else if (c > 4) { c -= 5; rem0[i] -= 5.0f; }
        rank[i] = c;
    }

    float b[6] = {0.f, 0.f, 0.f, 0.f, 0.f, 0.f};
    #pragma unroll
    for (int i = 0; i < 5; i++) {
        float v = (e[i] - rem0[i]) / 5.0f;
        b[4 - rank[i]] += v;
        b[5 - rank[i]] -= v;
    }
    b[0] += 1.0f + b[5];
    #pragma unroll
    for (int r = 0; r < 5; r++) bary[r] = b[r];

    int cc0 = (int)rem0[0], cc1 = (int)rem0[1], cc2 = (int)rem0[2], cc3 = (int)rem0[3];
    #pragma unroll
    for (int r = 0; r < 5; r++) {
        int k0 = cc0 + ((rank[0] < 5 - r) ? r : r - 5);
        int k1 = cc1 + ((rank[1] < 5 - r) ? r : r - 5);
        int k2 = cc2 + ((rank[2] < 5 - r) ? r : r - 5);
        int k3 = cc3 + ((rank[3] < 5 - r) ? r : r - 5);
        keys[r] = packkey(k0, k1, k2, k3);
    }
}

// --- K0: clear hash + count -------------------------------------------------
__global__ void k_clear() {
    unsigned s = blockIdx.x * blockDim.x + threadIdx.x;
    if (s == 0) g_count = 0;
    if (s < HASH_SIZE) g_keys[s] = 0ull;
}

// --- K1: insert all keys ----------------------------------------------------
__global__ void k_build(const float* __restrict__ image) {
    int n = blockIdx.x * blockDim.x + threadIdx.x;
    if (n >= NPIX) return;
    unsigned long long keys[5];
    float bary[5];
    compute_lattice(n, image, keys, bary);
    #pragma unroll
    for (int r = 0; r < 5; r++) {
        unsigned long long key = keys[r];
        unsigned s = hash64(key);
        #pragma unroll 1
        while (true) {
            unsigned long long old = atomicCAS(&g_keys[s], 0ull, key);
            if (old == 0ull || old == key) break;
            s = (s + 1) & HASH_MASK;
        }
    }
}

// --- K2: compact occupied slots -> indices; zero their value rows -----------
__global__ void k_compact() {
    unsigned s = blockIdx.x * blockDim.x + threadIdx.x;
    if (s >= HASH_SIZE) return;
    unsigned long long key = g_keys[s];
    if (key != 0ull) {
        int idx = atomicAdd(&g_count, 1);
        g_slotidx[s] = idx;
        g_ckey[idx] = key;
        float4* v = reinterpret_cast<float4*>(&g_valsA[(size_t)idx * VSTRIDE]);
        v[0] = make_float4(0.f, 0.f, 0.f, 0.f);
        v[1] = make_float4(0.f, 0.f, 0.f, 0.f);
    }
}

// --- K3: splat + record per-pixel (idx, bary) -------------------------------
__global__ void k_scatter(const float* __restrict__ image, const float* __restrict__ input) {
    int n = blockIdx.x * blockDim.x + threadIdx.x;
    if (n >= NPIX) return;
    unsigned long long keys[5];
    float bary[5];
    compute_lattice(n, image, keys, bary);
    float q0 = input[0 * NPIX + n];
    float q1 = input[1 * NPIX + n];
    float q2 = input[2 * NPIX + n];
    float q3 = input[3 * NPIX + n];
    #pragma unroll
    for (int r = 0; r < 5; r++) {
        int idx = hash_lookup(keys[r]);
        g_pixidx[r * NPIX + n] = idx;
        g_pixbary[r * NPIX + n] = bary[r];
        float w = bary[r];
        float* base = &g_valsA[(size_t)idx * VSTRIDE];
        atomicAdd(base + 0, w * q0);
        atomicAdd(base + 1, w * q1);
        atomicAdd(base + 2, w * q2);
        atomicAdd(base + 3, w * q3);
        atomicAdd(base + 4, w);
    }
}

// --- K4..8: one blur sweep along lattice direction (delta = packed offset) --
__global__ void k_blur(const float* __restrict__ src, float* __restrict__ dst,
                       unsigned long long delta) {
    int e = blockIdx.x * blockDim.x + threadIdx.x;
    if (e >= g_count) return;
    unsigned long long key = g_ckey[e];
    int i1 = hash_lookup(key + delta);
    int i2 = hash_lookup(key - delta);

    const float* s0 = &src[(size_t)e * VSTRIDE];
    float o0 = 0.5f * s0[0];
    float o1 = 0.5f * s0[1];
    float o2 = 0.5f * s0[2];
    float o3 = 0.5f * s0[3];
    float o4 = 0.5f * s0[4];
    if (i1 >= 0) {
        const float* p = &src[(size_t)i1 * VSTRIDE];
        o0 += 0.25f * p[0]; o1 += 0.25f * p[1]; o2 += 0.25f * p[2];
        o3 += 0.25f * p[3]; o4 += 0.25f * p[4];
    }
    if (i2 >= 0) {
        const float* p = &src[(size_t)i2 * VSTRIDE];
        o0 += 0.25f * p[0]; o1 += 0.25f * p[1]; o2 += 0.25f * p[2];
        o3 += 0.25f * p[3]; o4 += 0.25f * p[4];
    }
    float* d = &dst[(size_t)e * VSTRIDE];
    d[0] = o0; d[1] = o1; d[2] = o2; d[3] = o3; d[4] = o4;
}

// --- K9: slice + normalize ---------------------------------------------------
__global__ void k_slice(const float* __restrict__ vals, float* __restrict__ out) {
    int n = blockIdx.x * blockDim.x + threadIdx.x;
    if (n >= NPIX) return;
    float a0 = 0.f, a1 = 0.f, a2 = 0.f, a3 = 0.f, a4 = 0.f;
    #pragma unroll
    for (int r = 0; r < 5; r++) {
        int idx = g_pixidx[r * NPIX + n];
        float w = g_pixbary[r * NPIX + n];
        const float* p = &vals[(size_t)idx * VSTRIDE];
        a0 += w * p[0];
        a1 += w * p[1];
        a2 += w * p[2];
        a3 += w * p[3];
        a4 += w * p[4];
    }
    float den = a4 + EPS64;
    out[0 * NPIX + n] = a0 / den;
    out[1 * NPIX + n] = a1 / den;
    out[2 * NPIX + n] = a2 / den;
    out[3 * NPIX + n] = a3 / den;
}

// ---------------------------------------------------------------------------

extern "C" void kernel_launch(void* const* d_in, const int* in_sizes, int n_in,
                              void* d_out, int out_size) {
    // Identify inputs by size (input_ = 4*NPIX, image = NPIX).
    const float* input = (const float*)d_in[0];
    const float* image = (const float*)d_in[1];
    if (n_in >= 2 && in_sizes[0] == NPIX) {
        image = (const float*)d_in[0];
        input = (const float*)d_in[1];
    }
    float* out = (float*)d_out;

    const int TB = 256;

    // Packed key deltas for the 5 blur directions (field-local, no carries).
    const long long F0 = 1ll << 48, F1 = 1ll << 32, F2 = 1ll << 16, F3 = 1ll;
    unsigned long long deltas[5];
    deltas[0] = (unsigned long long)(-4 * F0 + F1 + F2 + F3);
    deltas[1] = (unsigned long long)(F0 - 4 * F1 + F2 + F3);
    deltas[2] = (unsigned long long)(F0 + F1 - 4 * F2 + F3);
    deltas[3] = (unsigned long long)(F0 + F1 + F2 - 4 * F3);
    deltas[4] = (unsigned long long)(F0 + F1 + F2 + F3);

    // Grab raw device pointers of the value buffers for ping-pong.
    float *valsA, *valsB;
    cudaGetSymbolAddress((void**)&valsA, g_valsA);
    cudaGetSymbolAddress((void**)&valsB, g_valsB);

    k_clear<<<HASH_SIZE / TB, TB>>>();
    k_build<<<NBLK, TB>>>(image);
    k_compact<<<HASH_SIZE / TB, TB>>>();
    k_scatter<<<NBLK, TB>>>(image, input);

    const int MBLK = (MAXM + TB - 1) / TB;
    float* src = valsA;
    float* dst = valsB;
    for (int j = 0; j < 5; j++) {
        k_blur<<<MBLK, TB>>>(src, dst, deltas[j]);
        float* tmp = src; src = dst; dst = tmp;
    }
    // after 5 passes, result is in `src`
    k_slice<<<NBLK, TB>>>(src, out);
}

// round 2
// speedup vs baseline: 1.4359x; 1.4359x over previous
#include <cuda_runtime.h>

// ---------------------------------------------------------------------------
// Permutohedral-lattice bilateral filter, d=4 (z,y,x,intensity), dp1=5.
// Input: input_ (4,96,96,96) f32;  image (1,96,96,96) f32. Output (4,96,96,96).
// ---------------------------------------------------------------------------

#define DIMX 96
#define NPIX (96*96*96)          // 884736
#define NBLK ((NPIX + 255) / 256)

#define HASH_BITS 23
#define HASH_SIZE (1u << HASH_BITS)   // 8388608 slots > 5*NPIX max keys
#define HASH_MASK (HASH_SIZE - 1u)
#define MAXM 4500000                  // >= 5*NPIX = 4423680
#define VSTRIDE 8                     // 32B-aligned per-vertex value row (5 used)

#define SC0 2.886751345948129f   // sqrt(2/3)*5/sqrt(2)
#define SC1 1.6666666666666667f  // sqrt(2/3)*5/sqrt(6)
#define SC2 1.1785113019775793f  // sqrt(2/3)*5/sqrt(12)
#define SC3 0.9128709291752769f  // sqrt(2/3)*5/sqrt(20)
#define EPS64 2.220446049250313e-16f

__device__ unsigned long long g_keys[HASH_SIZE];
__device__ int                g_slotidx[HASH_SIZE];
__device__ unsigned long long g_ckey[MAXM];
__device__ float              g_valsA[(size_t)MAXM * VSTRIDE];
__device__ float              g_valsB[(size_t)MAXM * VSTRIDE];
__device__ int                g_pixmap[NPIX * 5];   // build: hash slot; scatter rewrites: compact idx
__device__ float              g_pixbary[NPIX * 5];
__device__ int                g_count;

__device__ __forceinline__ unsigned hash64(unsigned long long k) {
    k *= 0x9E3779B97F4A7C15ull;
    return (unsigned)(k >> (64 - HASH_BITS));
}

__device__ __forceinline__ unsigned long long packkey(int c0, int c1, int c2, int c3) {
    return (((unsigned long long)(unsigned)(c0 + 2048)) << 48)
         | (((unsigned long long)(unsigned)(c1 + 2048)) << 32)
         | (((unsigned long long)(unsigned)(c2 + 2048)) << 16)
         |  ((unsigned long long)(unsigned)(c3 + 2048));
}

// Read-only probe. Returns compact index or -1 (miss). Used by blur only.
__device__ __forceinline__ int hash_lookup(unsigned long long key) {
    unsigned s = hash64(key);
    #pragma unroll 1
    while (true) {
        unsigned long long k = g_keys[s];
        if (k == key) return g_slotidx[s];
        if (k == 0ull) return -1;
        s = (s + 1) & HASH_MASK;
    }
}

__device__ __forceinline__ void red_add_v4(float* addr, float a, float b, float c, float d) {
    asm volatile("red.global.add.v4.f32 [%0], {%1, %2, %3, %4};"
                 :: "l"(addr), "f"(a), "f"(b), "f"(c), "f"(d) : "memory");
}
__device__ __forceinline__ void red_add_f(float* addr, float a) {
    asm volatile("red.global.add.f32 [%0], %1;" :: "l"(addr), "f"(a) : "memory");
}

// Exact fp32 replication of the reference elevation/rank/bary/key math.
__device__ __forceinline__ void compute_lattice(int n, const float* __restrict__ image,
                                                unsigned long long keys[5], float bary[5]) {
    int x = n % DIMX;
    int t = n / DIMX;
    int y = t % DIMX;
    int z = t / DIMX;

    float cf0 = ((float)z / 5.0f) * SC0;
    float cf1 = ((float)y / 5.0f) * SC1;
    float cf2 = ((float)x / 5.0f) * SC2;
    float cf3 = (image[n] * 4.0f) * SC3;   // image / 0.25

    float e[5];
    float sm = 0.0f;
    e[4] = sm - 4.0f * cf3; sm += cf3;
    e[3] = sm - 3.0f * cf2; sm += cf2;
    e[2] = sm - 2.0f * cf1; sm += cf1;
    e[1] = sm - 1.0f * cf0; sm += cf0;
    e[0] = sm;

    float rem0[5], diff[5];
    int sum_rd = 0;
    #pragma unroll
    for (int i = 0; i < 5; i++) {
        float rd = rintf(e[i] / 5.0f);      // round-half-even, matches jnp.round
        rem0[i] = rd * 5.0f;
        diff[i] = e[i] - rem0[i];
        sum_rd += (int)rd;
    }

    int rank[5];
    #pragma unroll
    for (int i = 0; i < 5; i++) {
        int c = 0;
        #pragma unroll
        for (int j = 0; j < 5; j++)
            c += (diff[j] > diff[i]) || ((diff[j] == diff[i]) && (j < i));
        c += sum_rd;
        if (c < 0)      { c += 5; rem0[i] += 5.0f; }
        else if (c > 4) { c -= 5; rem0[i] -= 5.0f; }
        rank[i] = c;
    }

    float b[6] = {0.f, 0.f, 0.f, 0.f, 0.f, 0.f};
    #pragma unroll
    for (int i = 0; i < 5; i++) {
        float v = (e[i] - rem0[i]) / 5.0f;
        b[4 - rank[i]] += v;
        b[5 - rank[i]] -= v;
    }
    b[0] += 1.0f + b[5];
    #pragma unroll
    for (int r = 0; r < 5; r++) bary[r] = b[r];

    int cc0 = (int)rem0[0], cc1 = (int)rem0[1], cc2 = (int)rem0[2], cc3 = (int)rem0[3];
    #pragma unroll
    for (int r = 0; r < 5; r++) {
        int k0 = cc0 + ((rank[0] < 5 - r) ? r : r - 5);
        int k1 = cc1 + ((rank[1] < 5 - r) ? r : r - 5);
        int k2 = cc2 + ((rank[2] < 5 - r) ? r : r - 5);
        int k3 = cc3 + ((rank[3] < 5 - r) ? r : r - 5);
        keys[r] = packkey(k0, k1, k2, k3);
    }
}

// --- K0: clear hash + count -------------------------------------------------
__global__ void k_clear() {
    unsigned s = blockIdx.x * blockDim.x + threadIdx.x;
    if (s == 0) g_count = 0;
    if (s < HASH_SIZE) g_keys[s] = 0ull;
}

// --- K1: insert all keys; record final slot + bary per (pixel, corner) ------
// Slots transition 0 -> key exactly once, so a (possibly stale) plain load is
// safe as a fast path: stale 0 falls through to the coherent CAS.
__global__ void k_build(const float* __restrict__ image) {
    int n = blockIdx.x * blockDim.x + threadIdx.x;
    if (n >= NPIX) return;
    unsigned long long keys[5];
    float bary[5];
    compute_lattice(n, image, keys, bary);
    #pragma unroll
    for (int r = 0; r < 5; r++) {
        unsigned long long key = keys[r];
        unsigned s = hash64(key);
        #pragma unroll 1
        while (true) {
            unsigned long long k = g_keys[s];
            if (k == key) break;
            if (k == 0ull) {
                unsigned long long old = atomicCAS(&g_keys[s], 0ull, key);
                if (old == 0ull || old == key) break;
            }
            s = (s + 1) & HASH_MASK;
        }
        g_pixmap[r * NPIX + n] = (int)s;
        g_pixbary[r * NPIX + n] = bary[r];
    }
}

// --- K2: compact occupied slots -> indices; zero their value rows -----------
__global__ void k_compact() {
    unsigned s = blockIdx.x * blockDim.x + threadIdx.x;
    if (s >= HASH_SIZE) return;
    unsigned long long key = g_keys[s];
    if (key != 0ull) {
        int idx = atomicAdd(&g_count, 1);
        g_slotidx[s] = idx;
        g_ckey[idx] = key;
        float4* v = reinterpret_cast<float4*>(&g_valsA[(size_t)idx * VSTRIDE]);
        v[0] = make_float4(0.f, 0.f, 0.f, 0.f);
        v[1] = make_float4(0.f, 0.f, 0.f, 0.f);
    }
}

// --- K3: splat (vector atomics); rewrite pixmap slot -> compact idx ---------
__global__ void k_scatter(const float* __restrict__ input) {
    int n = blockIdx.x * blockDim.x + threadIdx.x;
    if (n >= NPIX) return;
    float q0 = input[0 * NPIX + n];
    float q1 = input[1 * NPIX + n];
    float q2 = input[2 * NPIX + n];
    float q3 = input[3 * NPIX + n];
    #pragma unroll
    for (int r = 0; r < 5; r++) {
        int s = g_pixmap[r * NPIX + n];
        int idx = g_slotidx[s];
        g_pixmap[r * NPIX + n] = idx;
        float w = g_pixbary[r * NPIX + n];
        float* base = &g_valsA[(size_t)idx * VSTRIDE];
        red_add_v4(base, w * q0, w * q1, w * q2, w * q3);
        red_add_f(base + 4, w);
    }
}

// --- K4..8: one blur sweep along lattice direction (delta = packed offset) --
__global__ void k_blur(const float* __restrict__ src, float* __restrict__ dst,
                       unsigned long long delta) {
    int e = blockIdx.x * blockDim.x + threadIdx.x;
    if (e >= g_count) return;
    unsigned long long key = g_ckey[e];
    int i1 = hash_lookup(key + delta);
    int i2 = hash_lookup(key - delta);

    const float4* s0 = reinterpret_cast<const float4*>(&src[(size_t)e * VSTRIDE]);
    float4 a = s0[0];
    float  a4 = src[(size_t)e * VSTRIDE + 4];
    float o0 = 0.5f * a.x, o1 = 0.5f * a.y, o2 = 0.5f * a.z, o3 = 0.5f * a.w;
    float o4 = 0.5f * a4;
    if (i1 >= 0) {
        const float4* p = reinterpret_cast<const float4*>(&src[(size_t)i1 * VSTRIDE]);
        float4 b = p[0];
        float  b4 = src[(size_t)i1 * VSTRIDE + 4];
        o0 += 0.25f * b.x; o1 += 0.25f * b.y; o2 += 0.25f * b.z; o3 += 0.25f * b.w;
        o4 += 0.25f * b4;
    }
    if (i2 >= 0) {
        const float4* p = reinterpret_cast<const float4*>(&src[(size_t)i2 * VSTRIDE]);
        float4 b = p[0];
        float  b4 = src[(size_t)i2 * VSTRIDE + 4];
        o0 += 0.25f * b.x; o1 += 0.25f * b.y; o2 += 0.25f * b.z; o3 += 0.25f * b.w;
        o4 += 0.25f * b4;
    }
    float4* d = reinterpret_cast<float4*>(&dst[(size_t)e * VSTRIDE]);
    d[0] = make_float4(o0, o1, o2, o3);
    dst[(size_t)e * VSTRIDE + 4] = o4;
}

// --- K9: slice + normalize ---------------------------------------------------
__global__ void k_slice(const float* __restrict__ vals, float* __restrict__ out) {
    int n = blockIdx.x * blockDim.x + threadIdx.x;
    if (n >= NPIX) return;
    float a0 = 0.f, a1 = 0.f, a2 = 0.f, a3 = 0.f, a4 = 0.f;
    #pragma unroll
    for (int r = 0; r < 5; r++) {
        int idx = g_pixmap[r * NPIX + n];
        float w = g_pixbary[r * NPIX + n];
        const float4* p = reinterpret_cast<const float4*>(&vals[(size_t)idx * VSTRIDE]);
        float4 v = p[0];
        float  v4 = vals[(size_t)idx * VSTRIDE + 4];
        a0 += w * v.x;
        a1 += w * v.y;
        a2 += w * v.z;
        a3 += w * v.w;
        a4 += w * v4;
    }
    float den = a4 + EPS64;
    out[0 * NPIX + n] = a0 / den;
    out[1 * NPIX + n] = a1 / den;
    out[2 * NPIX + n] = a2 / den;
    out[3 * NPIX + n] = a3 / den;
}

// ---------------------------------------------------------------------------

extern "C" void kernel_launch(void* const* d_in, const int* in_sizes, int n_in,
                              void* d_out, int out_size) {
    const float* input = (const float*)d_in[0];
    const float* image = (const float*)d_in[1];
    if (n_in >= 2 && in_sizes[0] == NPIX) {
        image = (const float*)d_in[0];
        input = (const float*)d_in[1];
    }
    float* out = (float*)d_out;

    const int TB = 256;

    // Packed key deltas for the 5 blur directions (field-local, no carries).
    const long long F0 = 1ll << 48, F1 = 1ll << 32, F2 = 1ll << 16, F3 = 1ll;
    unsigned long long deltas[5];
    deltas[0] = (unsigned long long)(-4 * F0 + F1 + F2 + F3);
    deltas[1] = (unsigned long long)(F0 - 4 * F1 + F2 + F3);
    deltas[2] = (unsigned long long)(F0 + F1 - 4 * F2 + F3);
    deltas[3] = (unsigned long long)(F0 + F1 + F2 - 4 * F3);
    deltas[4] = (unsigned long long)(F0 + F1 + F2 + F3);

    float *valsA, *valsB;
    cudaGetSymbolAddress((void**)&valsA, g_valsA);
    cudaGetSymbolAddress((void**)&valsB, g_valsB);

    k_clear<<<HASH_SIZE / TB, TB>>>();
    k_build<<<NBLK, TB>>>(image);
    k_compact<<<HASH_SIZE / TB, TB>>>();
    k_scatter<<<NBLK, TB>>>(input);

    const int MBLK = (MAXM + TB - 1) / TB;
    float* src = valsA;
    float* dst = valsB;
    for (int j = 0; j < 5; j++) {
        k_blur<<<MBLK, TB>>>(src, dst, deltas[j]);
        float* tmp = src; src = dst; dst = tmp;
    }
    k_slice<<<NBLK, TB>>>(src, out);
}

// round 3
// speedup vs baseline: 1.8934x; 1.3186x over previous
#include <cuda_runtime.h>

// ---------------------------------------------------------------------------
// Permutohedral-lattice bilateral filter, d=4 (z,y,x,intensity), dp1=5.
// Input: input_ (4,96,96,96) f32;  image (1,96,96,96) f32. Output (4,96,96,96).
// ---------------------------------------------------------------------------

#define DIMX 96
#define NPIX (96*96*96)          // 884736
#define NBLK ((NPIX + 255) / 256)

#define HASH_BITS 23
#define HASH_SIZE (1u << HASH_BITS)   // 8388608 slots > 5*NPIX max keys
#define HASH_MASK (HASH_SIZE - 1u)
#define MAXM 4500000                  // >= 5*NPIX = 4423680

#define SC0 2.886751345948129f   // sqrt(2/3)*5/sqrt(2)
#define SC1 1.6666666666666667f  // sqrt(2/3)*5/sqrt(6)
#define SC2 1.1785113019775793f  // sqrt(2/3)*5/sqrt(12)
#define SC3 0.9128709291752769f  // sqrt(2/3)*5/sqrt(20)
#define EPS64 2.220446049250313e-16f

__device__ unsigned long long g_keys[HASH_SIZE];
__device__ int                g_slotidx[HASH_SIZE];
__device__ unsigned long long g_ckey[MAXM];
__device__ float4             g_v4A[MAXM];
__device__ float4             g_v4B[MAXM];
__device__ float              g_v1A[MAXM];
__device__ float              g_v1B[MAXM];
__device__ uint2              g_pixrec[NPIX * 5];   // .x: slot (build) -> idx (scatter); .y: bary bits
__device__ int                g_count;

__device__ __forceinline__ unsigned hash64(unsigned long long k) {
    k *= 0x9E3779B97F4A7C15ull;
    return (unsigned)(k >> (64 - HASH_BITS));
}

__device__ __forceinline__ unsigned long long packkey(int c0, int c1, int c2, int c3) {
    return (((unsigned long long)(unsigned)(c0 + 2048)) << 48)
         | (((unsigned long long)(unsigned)(c1 + 2048)) << 32)
         | (((unsigned long long)(unsigned)(c2 + 2048)) << 16)
         |  ((unsigned long long)(unsigned)(c3 + 2048));
}

// Read-only probe. Returns compact index or -1 (miss). Used by blur only.
__device__ __forceinline__ int hash_lookup(unsigned long long key) {
    unsigned s = hash64(key);
    #pragma unroll 1
    while (true) {
        unsigned long long k = g_keys[s];
        if (k == key) return g_slotidx[s];
        if (k == 0ull) return -1;
        s = (s + 1) & HASH_MASK;
    }
}

__device__ __forceinline__ void red_add_v4(float4* addr, float a, float b, float c, float d) {
    asm volatile("red.global.add.v4.f32 [%0], {%1, %2, %3, %4};"
                 :: "l"(addr), "f"(a), "f"(b), "f"(c), "f"(d) : "memory");
}
__device__ __forceinline__ void red_add_f(float* addr, float a) {
    asm volatile("red.global.add.f32 [%0], %1;" :: "l"(addr), "f"(a) : "memory");
}

// Exact fp32 replication of the reference elevation/rank/bary/key math.
__device__ __forceinline__ void compute_lattice(int n, const float* __restrict__ image,
                                                unsigned long long keys[5], float bary[5]) {
    int x = n % DIMX;
    int t = n / DIMX;
    int y = t % DIMX;
    int z = t / DIMX;

    float cf0 = ((float)z / 5.0f) * SC0;
    float cf1 = ((float)y / 5.0f) * SC1;
    float cf2 = ((float)x / 5.0f) * SC2;
    float cf3 = (image[n] * 4.0f) * SC3;   // image / 0.25

    float e[5];
    float sm = 0.0f;
    e[4] = sm - 4.0f * cf3; sm += cf3;
    e[3] = sm - 3.0f * cf2; sm += cf2;
    e[2] = sm - 2.0f * cf1; sm += cf1;
    e[1] = sm - 1.0f * cf0; sm += cf0;
    e[0] = sm;

    float rem0[5], diff[5];
    int sum_rd = 0;
    #pragma unroll
    for (int i = 0; i < 5; i++) {
        float rd = rintf(e[i] / 5.0f);      // round-half-even, matches jnp.round
        rem0[i] = rd * 5.0f;
        diff[i] = e[i] - rem0[i];
        sum_rd += (int)rd;
    }

    int rank[5];
    #pragma unroll
    for (int i = 0; i < 5; i++) {
        int c = 0;
        #pragma unroll
        for (int j = 0; j < 5; j++)
            c += (diff[j] > diff[i]) || ((diff[j] == diff[i]) && (j < i));
        c += sum_rd;
        if (c < 0)      { c += 5; rem0[i] += 5.0f; }
        else if (c > 4) { c -= 5; rem0[i] -= 5.0f; }
        rank[i] = c;
    }

    float b[6] = {0.f, 0.f, 0.f, 0.f, 0.f, 0.f};
    #pragma unroll
    for (int i = 0; i < 5; i++) {
        float v = (e[i] - rem0[i]) / 5.0f;
        b[4 - rank[i]] += v;
        b[5 - rank[i]] -= v;
    }
    b[0] += 1.0f + b[5];
    #pragma unroll
    for (int r = 0; r < 5; r++) bary[r] = b[r];

    int cc0 = (int)rem0[0], cc1 = (int)rem0[1], cc2 = (int)rem0[2], cc3 = (int)rem0[3];
    #pragma unroll
    for (int r = 0; r < 5; r++) {
        int k0 = cc0 + ((rank[0] < 5 - r) ? r : r - 5);
        int k1 = cc1 + ((rank[1] < 5 - r) ? r : r - 5);
        int k2 = cc2 + ((rank[2] < 5 - r) ? r : r - 5);
        int k3 = cc3 + ((rank[3] < 5 - r) ? r : r - 5);
        keys[r] = packkey(k0, k1, k2, k3);
    }
}

// --- K0: clear hash (16B stores) + count -------------------------------------
__global__ void k_clear() {
    unsigned i = blockIdx.x * blockDim.x + threadIdx.x;
    if (i == 0) g_count = 0;
    if (i < HASH_SIZE / 2) {
        reinterpret_cast<ulonglong2*>(g_keys)[i] = make_ulonglong2(0ull, 0ull);
    }
}

// --- K1: insert keys; assign compact index + zero row at insert;
//         record (slot, bary) per (pixel, corner). ---------------------------
// Slots transition 0 -> key exactly once, so a (possibly stale) plain load is
// safe as a fast path: stale 0 falls through to the coherent CAS.
__global__ void k_build(const float* __restrict__ image) {
    int n = blockIdx.x * blockDim.x + threadIdx.x;
    if (n >= NPIX) return;
    unsigned long long keys[5];
    float bary[5];
    compute_lattice(n, image, keys, bary);
    #pragma unroll
    for (int r = 0; r < 5; r++) {
        unsigned long long key = keys[r];
        unsigned s = hash64(key);
        #pragma unroll 1
        while (true) {
            unsigned long long k = g_keys[s];
            if (k == key) break;
            if (k == 0ull) {
                unsigned long long old = atomicCAS(&g_keys[s], 0ull, key);
                if (old == 0ull) {
                    int idx = atomicAdd(&g_count, 1);
                    g_slotidx[s] = idx;
                    g_ckey[idx] = key;
                    g_v4A[idx] = make_float4(0.f, 0.f, 0.f, 0.f);
                    g_v1A[idx] = 0.f;
                    break;
                }
                if (old == key) break;
            }
            s = (s + 1) & HASH_MASK;
        }
        g_pixrec[r * NPIX + n] = make_uint2(s, __float_as_uint(bary[r]));
    }
}

// --- K2: splat (vector atomics); rewrite pixrec slot -> compact idx ---------
__global__ void k_scatter(const float* __restrict__ input) {
    int n = blockIdx.x * blockDim.x + threadIdx.x;
    if (n >= NPIX) return;
    float q0 = input[0 * NPIX + n];
    float q1 = input[1 * NPIX + n];
    float q2 = input[2 * NPIX + n];
    float q3 = input[3 * NPIX + n];
    #pragma unroll
    for (int r = 0; r < 5; r++) {
        uint2 rec = g_pixrec[r * NPIX + n];
        int idx = g_slotidx[rec.x];
        g_pixrec[r * NPIX + n].x = (unsigned)idx;
        float w = __uint_as_float(rec.y);
        red_add_v4(&g_v4A[idx], w * q0, w * q1, w * q2, w * q3);
        red_add_f(&g_v1A[idx], w);
    }
}

// --- K3..7: one blur sweep (grid-stride over actual vertex count) -----------
__global__ void k_blur(const float4* __restrict__ s4, const float* __restrict__ s1,
                       float4* __restrict__ d4, float* __restrict__ d1,
                       unsigned long long delta) {
    int total = g_count;
    for (int e = blockIdx.x * blockDim.x + threadIdx.x; e < total;
         e += gridDim.x * blockDim.x) {
        unsigned long long key = g_ckey[e];
        int i1 = hash_lookup(key + delta);
        int i2 = hash_lookup(key - delta);

        float4 a = s4[e];
        float  a4 = s1[e];
        float o0 = 0.5f * a.x, o1 = 0.5f * a.y, o2 = 0.5f * a.z, o3 = 0.5f * a.w;
        float o4 = 0.5f * a4;
        if (i1 >= 0) {
            float4 b = s4[i1];
            float  b4 = s1[i1];
            o0 += 0.25f * b.x; o1 += 0.25f * b.y; o2 += 0.25f * b.z; o3 += 0.25f * b.w;
            o4 += 0.25f * b4;
        }
        if (i2 >= 0) {
            float4 b = s4[i2];
            float  b4 = s1[i2];
            o0 += 0.25f * b.x; o1 += 0.25f * b.y; o2 += 0.25f * b.z; o3 += 0.25f * b.w;
            o4 += 0.25f * b4;
        }
        d4[e] = make_float4(o0, o1, o2, o3);
        d1[e] = o4;
    }
}

// --- K8: slice + normalize ----------------------------------------------------
__global__ void k_slice(const float4* __restrict__ v4, const float* __restrict__ v1,
                        float* __restrict__ out) {
    int n = blockIdx.x * blockDim.x + threadIdx.x;
    if (n >= NPIX) return;
    float a0 = 0.f, a1 = 0.f, a2 = 0.f, a3 = 0.f, a4 = 0.f;
    #pragma unroll
    for (int r = 0; r < 5; r++) {
        uint2 rec = g_pixrec[r * NPIX + n];
        int idx = (int)rec.x;
        float w = __uint_as_float(rec.y);
        float4 v = v4[idx];
        float  vv = v1[idx];
        a0 += w * v.x;
        a1 += w * v.y;
        a2 += w * v.z;
        a3 += w * v.w;
        a4 += w * vv;
    }
    float den = a4 + EPS64;
    out[0 * NPIX + n] = a0 / den;
    out[1 * NPIX + n] = a1 / den;
    out[2 * NPIX + n] = a2 / den;
    out[3 * NPIX + n] = a3 / den;
}

// ---------------------------------------------------------------------------

extern "C" void kernel_launch(void* const* d_in, const int* in_sizes, int n_in,
                              void* d_out, int out_size) {
    const float* input = (const float*)d_in[0];
    const float* image = (const float*)d_in[1];
    if (n_in >= 2 && in_sizes[0] == NPIX) {
        image = (const float*)d_in[0];
        input = (const float*)d_in[1];
    }
    float* out = (float*)d_out;

    const int TB = 256;

    // Packed key deltas for the 5 blur directions (field-local, no carries).
    const long long F0 = 1ll << 48, F1 = 1ll << 32, F2 = 1ll << 16, F3 = 1ll;
    unsigned long long deltas[5];
    deltas[0] = (unsigned long long)(-4 * F0 + F1 + F2 + F3);
    deltas[1] = (unsigned long long)(F0 - 4 * F1 + F2 + F3);
    deltas[2] = (unsigned long long)(F0 + F1 - 4 * F2 + F3);
    deltas[3] = (unsigned long long)(F0 + F1 + F2 - 4 * F3);
    deltas[4] = (unsigned long long)(F0 + F1 + F2 + F3);

    float4 *v4A, *v4B; float *v1A, *v1B;
    cudaGetSymbolAddress((void**)&v4A, g_v4A);
    cudaGetSymbolAddress((void**)&v4B, g_v4B);
    cudaGetSymbolAddress((void**)&v1A, g_v1A);
    cudaGetSymbolAddress((void**)&v1B, g_v1B);

    k_clear<<<(HASH_SIZE / 2) / TB, TB>>>();
    k_build<<<NBLK, TB>>>(image);
    k_scatter<<<NBLK, TB>>>(input);

    // Persistent-style grid for blur: adapts to actual vertex count.
    const int BBLK = 148 * 16;
    float4* s4 = v4A; float* s1 = v1A;
    float4* d4 = v4B; float* d1 = v1B;
    for (int j = 0; j < 5; j++) {
        k_blur<<<BBLK, TB>>>(s4, s1, d4, d1, deltas[j]);
        float4* t4 = s4; s4 = d4; d4 = t4;
        float*  t1 = s1; s1 = d1; d1 = t1;
    }
    k_slice<<<NBLK, TB>>>(s4, s1, out);
}

// round 4
// speedup vs baseline: 2.6476x; 1.3983x over previous
#include <cuda_runtime.h>

// ---------------------------------------------------------------------------
// Permutohedral-lattice bilateral filter, d=4 (z,y,x,intensity), dp1=5.
// Direct-mapped lattice table (no hashing): every lattice key has all 4
// coords == r (mod 5); key = 5*b + r with b in a small box (interval-proven).
// ---------------------------------------------------------------------------

#define DIMX 96
#define NPIX (96*96*96)          // 884736
#define NBLK ((NPIX + 255) / 256)

// b-field boxes (include +-4 probe slack and >=1 pad on each face)
#define R_SZ0 36
#define R_SZ1 36
#define R_SZ2 28
#define R_SZ3 26
#define OFF0 6
#define OFF1 17
#define OFF2 18
#define OFF3 19
#define S_B3 1
#define S_B2 (R_SZ3)              // 26
#define S_B1 (R_SZ2*R_SZ3)        // 728
#define S_B0 (R_SZ1*R_SZ2*R_SZ3)  // 26208
#define S_R  (R_SZ0*S_B0)         // 943488
#define TBL  (5*S_R)              // 4717440
#define SUM_SB (S_B0+S_B1+S_B2+S_B3)  // 26963

#define SC0 2.886751345948129f   // sqrt(2/3)*5/sqrt(2)
#define SC1 1.6666666666666667f  // sqrt(2/3)*5/sqrt(6)
#define SC2 1.1785113019775793f  // sqrt(2/3)*5/sqrt(12)
#define SC3 0.9128709291752769f  // sqrt(2/3)*5/sqrt(20)
#define EPS64 2.220446049250313e-16f

// Zero-initialized at module load. Unoccupied value rows are NEVER written,
// so they remain zero across all launches (blur reads them as "missing"=0).
__device__ unsigned g_tbl[TBL];          // occupancy marks (cleared per launch)
__device__ unsigned g_plist[TBL];        // compact list: pos | (r<<24)
__device__ float4   g_v4A[TBL];
__device__ float4   g_v4B[TBL];
__device__ float    g_v1A[TBL];
__device__ float    g_v1B[TBL];
__device__ uint2    g_pixrec[NPIX * 5];  // (.x = table pos, .y = bary bits)
__device__ int      g_count;

__device__ __forceinline__ void red_add_v4(float4* addr, float a, float b, float c, float d) {
    asm volatile("red.global.add.v4.f32 [%0], {%1, %2, %3, %4};"
                 :: "l"(addr), "f"(a), "f"(b), "f"(c), "f"(d) : "memory");
}
__device__ __forceinline__ void red_add_f(float* addr, float a) {
    asm volatile("red.global.add.f32 [%0], %1;" :: "l"(addr), "f"(a) : "memory");
}

// Exact fp32 replication of the reference elevation/rank/bary math.
// Outputs table position + bary per corner.
__device__ __forceinline__ void compute_lattice(int n, const float* __restrict__ image,
                                                int pos[5], float bary[5]) {
    int x = n % DIMX;
    int t = n / DIMX;
    int y = t % DIMX;
    int z = t / DIMX;

    float cf0 = ((float)z / 5.0f) * SC0;
    float cf1 = ((float)y / 5.0f) * SC1;
    float cf2 = ((float)x / 5.0f) * SC2;
    float cf3 = (image[n] * 4.0f) * SC3;   // image / 0.25

    float e[5];
    float sm = 0.0f;
    e[4] = sm - 4.0f * cf3; sm += cf3;
    e[3] = sm - 3.0f * cf2; sm += cf2;
    e[2] = sm - 2.0f * cf1; sm += cf1;
    e[1] = sm - 1.0f * cf0; sm += cf0;
    e[0] = sm;

    float rem0[5], diff[5];
    int sum_rd = 0;
    #pragma unroll
    for (int i = 0; i < 5; i++) {
        float rd = rintf(e[i] / 5.0f);      // round-half-even, matches jnp.round
        rem0[i] = rd * 5.0f;
        diff[i] = e[i] - rem0[i];
        sum_rd += (int)rd;
    }

    int rank[5];
    #pragma unroll
    for (int i = 0; i < 5; i++) {
        int c = 0;
        #pragma unroll
        for (int j = 0; j < 5; j++)
            c += (diff[j] > diff[i]) || ((diff[j] == diff[i]) && (j < i));
        c += sum_rd;
        if (c < 0)      { c += 5; rem0[i] += 5.0f; }
        else if (c > 4) { c -= 5; rem0[i] -= 5.0f; }
        rank[i] = c;
    }

    float b[6] = {0.f, 0.f, 0.f, 0.f, 0.f, 0.f};
    #pragma unroll
    for (int i = 0; i < 5; i++) {
        float v = (e[i] - rem0[i]) / 5.0f;
        b[4 - rank[i]] += v;
        b[5 - rank[i]] -= v;
    }
    b[0] += 1.0f + b[5];
    #pragma unroll
    for (int r = 0; r < 5; r++) bary[r] = b[r];

    int cc0 = (int)rem0[0], cc1 = (int)rem0[1], cc2 = (int)rem0[2], cc3 = (int)rem0[3];
    #pragma unroll
    for (int r = 0; r < 5; r++) {
        int k0 = cc0 + ((rank[0] < 5 - r) ? r : r - 5);
        int k1 = cc1 + ((rank[1] < 5 - r) ? r : r - 5);
        int k2 = cc2 + ((rank[2] < 5 - r) ? r : r - 5);
        int k3 = cc3 + ((rank[3] < 5 - r) ? r : r - 5);
        // All k_i == r (mod 5); exact integer division.
        int b0 = (k0 - r) / 5 + OFF0;
        int b1 = (k1 - r) / 5 + OFF1;
        int b2 = (k2 - r) / 5 + OFF2;
        int b3 = (k3 - r) / 5 + OFF3;
        pos[r] = r * S_R + b0 * S_B0 + b1 * S_B1 + b2 * S_B2 + b3;
    }
}

// --- K0: clear occupancy table (16B stores) + count ---------------------------
__global__ void k_clear() {
    unsigned i = blockIdx.x * blockDim.x + threadIdx.x;
    if (i == 0) g_count = 0;
    if (i < TBL / 4) {
        reinterpret_cast<uint4*>(g_tbl)[i] = make_uint4(0u, 0u, 0u, 0u);
    }
}

// --- K1: mark occupied lattice points (plain racy stores, benign);
//         record (pos, bary) per (pixel, corner). -----------------------------
__global__ void k_build(const float* __restrict__ image) {
    int n = blockIdx.x * blockDim.x + threadIdx.x;
    if (n >= NPIX) return;
    int pos[5];
    float bary[5];
    compute_lattice(n, image, pos, bary);
    #pragma unroll
    for (int r = 0; r < 5; r++) {
        g_tbl[pos[r]] = 1u;
        g_pixrec[r * NPIX + n] = make_uint2((unsigned)pos[r], __float_as_uint(bary[r]));
    }
}

// --- K2: compact occupied positions; zero their A-rows ------------------------
__global__ void k_compact() {
    int pos = blockIdx.x * blockDim.x + threadIdx.x;
    if (pos >= TBL) return;
    if (g_tbl[pos]) {
        int idx = atomicAdd(&g_count, 1);
        unsigned r = (unsigned)pos / (unsigned)S_R;
        g_plist[idx] = (unsigned)pos | (r << 24);
        g_v4A[pos] = make_float4(0.f, 0.f, 0.f, 0.f);
        g_v1A[pos] = 0.f;
    }
}

// --- K3: splat (vector atomics into pos-indexed rows) -------------------------
__global__ void k_scatter(const float* __restrict__ input) {
    int n = blockIdx.x * blockDim.x + threadIdx.x;
    if (n >= NPIX) return;
    float q0 = input[0 * NPIX + n];
    float q1 = input[1 * NPIX + n];
    float q2 = input[2 * NPIX + n];
    float q3 = input[3 * NPIX + n];
    #pragma unroll
    for (int r = 0; r < 5; r++) {
        uint2 rec = g_pixrec[r * NPIX + n];
        float w = __uint_as_float(rec.y);
        red_add_v4(&g_v4A[rec.x], w * q0, w * q1, w * q2, w * q3);
        red_add_f(&g_v1A[rec.x], w);
    }
}

// --- K4..8: one blur sweep. Neighbor address = pure integer delta on pos;
//            unoccupied neighbor rows are all-zero (never written). -----------
__global__ void k_blur(const float4* __restrict__ s4, const float* __restrict__ s1,
                       float4* __restrict__ d4, float* __restrict__ d1,
                       int dpn, int dpw, int dmn, int dmw) {
    int total = g_count;
    for (int e = blockIdx.x * blockDim.x + threadIdx.x; e < total;
         e += gridDim.x * blockDim.x) {
        unsigned p = g_plist[e];
        int pos = (int)(p & 0xFFFFFFu);
        unsigned r = p >> 24;
        int n1 = pos + ((r == 4u) ? dpw : dpn);
        int n2 = pos + ((r == 0u) ? dmw : dmn);

        float4 a = s4[pos];
        float  a4 = s1[pos];
        float4 b = s4[n1];
        float  b4 = s1[n1];
        float4 c = s4[n2];
        float  c4 = s1[n2];

        float4 o;
        o.x = 0.5f * a.x + 0.25f * (b.x + c.x);
        o.y = 0.5f * a.y + 0.25f * (b.y + c.y);
        o.z = 0.5f * a.z + 0.25f * (b.z + c.z);
        o.w = 0.5f * a.w + 0.25f * (b.w + c.w);
        float o4 = 0.5f * a4 + 0.25f * (b4 + c4);
        d4[pos] = o;
        d1[pos] = o4;
    }
}

// --- K9: slice + normalize ------------------------------------------------------
__global__ void k_slice(const float4* __restrict__ v4, const float* __restrict__ v1,
                        float* __restrict__ out) {
    int n = blockIdx.x * blockDim.x + threadIdx.x;
    if (n >= NPIX) return;
    float a0 = 0.f, a1 = 0.f, a2 = 0.f, a3 = 0.f, a4 = 0.f;
    #pragma unroll
    for (int r = 0; r < 5; r++) {
        uint2 rec = g_pixrec[r * NPIX + n];
        float w = __uint_as_float(rec.y);
        float4 v = v4[rec.x];
        float  vv = v1[rec.x];
        a0 += w * v.x;
        a1 += w * v.y;
        a2 += w * v.z;
        a3 += w * v.w;
        a4 += w * vv;
    }
    float den = a4 + EPS64;
    out[0 * NPIX + n] = a0 / den;
    out[1 * NPIX + n] = a1 / den;
    out[2 * NPIX + n] = a2 / den;
    out[3 * NPIX + n] = a3 / den;
}

// ---------------------------------------------------------------------------

extern "C" void kernel_launch(void* const* d_in, const int* in_sizes, int n_in,
                              void* d_out, int out_size) {
    const float* input = (const float*)d_in[0];
    const float* image = (const float*)d_in[1];
    if (n_in >= 2 && in_sizes[0] == NPIX) {
        image = (const float*)d_in[0];
        input = (const float*)d_in[1];
    }
    float* out = (float*)d_out;

    const int TB = 256;

    float4 *v4A, *v4B; float *v1A, *v1B;
    cudaGetSymbolAddress((void**)&v4A, g_v4A);
    cudaGetSymbolAddress((void**)&v4B, g_v4B);
    cudaGetSymbolAddress((void**)&v1A, g_v1A);
    cudaGetSymbolAddress((void**)&v1B, g_v1B);

    k_clear<<<(TBL / 4 + TB - 1) / TB, TB>>>();
    k_build<<<NBLK, TB>>>(image);
    k_compact<<<(TBL + TB - 1) / TB, TB>>>();
    k_scatter<<<NBLK, TB>>>(input);

    // Per-direction position deltas. s[j] = stride of the b-field that gets
    // the -4 coordinate step (0 for j=4: all coords +1).
    const int sj[5] = {S_B0, S_B1, S_B2, S_B3, 0};
    const int BBLK = 148 * 16;
    float4* s4 = v4A; float* s1 = v1A;
    float4* d4 = v4B; float* d1 = v1B;
    for (int j = 0; j < 5; j++) {
        int dpn = S_R - sj[j];                     // +dir, r<4
        int dpw = -4 * S_R + SUM_SB - sj[j];       // +dir, r==4
        int dmn = -S_R + sj[j];                    // -dir, r>0
        int dmw = 4 * S_R - SUM_SB + sj[j];        // -dir, r==0
        k_blur<<<BBLK, TB>>>(s4, s1, d4, d1, dpn, dpw, dmn, dmw);
        float4* t4 = s4; s4 = d4; d4 = t4;
        float*  t1 = s1; s1 = d1; d1 = t1;
    }
    k_slice<<<NBLK, TB>>>(s4, s1, out);
}